// round 13
// baseline (speedup 1.0000x reference)
#include <cuda_runtime.h>
#include <math.h>

// Problem constants
#define Bn   32
#define Nn   256
#define Hn   64
#define EPSf 1e-6f

// Table: KI intervals in d over [0, DMAX]; one float4 f-cubic each (power basis).
#define KI    256
#define DMAXf 20.0f

#define MAGICf 8388608.0f   // 2^23

// Device scratch (zero-init; restored each launch -> graph-replay safe)
__device__ float4   g_tab[KI];
__device__ float    g_v[Bn * Nn * 3];
__device__ float    g_bsum[Bn * 4];
__device__ unsigned g_ticket[Bn];

__device__ __forceinline__ float fast_tanh(float z)
{
    float az = fabsf(z);
    float e  = __expf(-2.f * az);
    float t  = __fdividef(1.f - e, 1.f + e);
    return copysignf(t, z);
}

// ---------------------------------------------------------------------------
// Kernel 1: table build. 32 blocks x 1024 threads; block owns 8 intervals
// (9 nodes, slots 0..8). W2 staged once per block (32 stagings total vs 128).
// ---------------------------------------------------------------------------
__global__ void __launch_bounds__(1024)
table_kernel(const float* __restrict__ t_in,
             const float* __restrict__ W1,   // (2,64)
             const float* __restrict__ b1,   // (64)
             const float* __restrict__ W2,   // (64,64)
             const float* __restrict__ b2,   // (64)
             const float* __restrict__ W3,   // (64,1)
             const float* __restrict__ b3)   // (1)
{
    const int tid = threadIdx.x;
    const int blk = blockIdx.x;

    __shared__ float  sW2[Hn * Hn];      // 16 KB
    __shared__ float2 sh1[9][Hn];
    __shared__ float2 s_node[10];
    __shared__ float  s_red[9][2][2];

    const float hstep = DMAXf / (float)KI;

    reinterpret_cast<float4*>(sW2)[tid] =
        reinterpret_cast<const float4*>(W2)[tid];

    const int slot = tid >> 6;        // 0..15; slots 0..8 active
    const int p    = tid & 63;
    const int node = blk * 8 + slot;  // max 31*8+8 = 256 ✓
    const float t  = t_in[0];
    const float d  = (float)node * hstep;

    if (slot < 9) {
        float w0 = W1[p];
        float z  = fmaf(d, w0, fmaf(t, W1[64 + p], b1[p]));
        float h1 = fast_tanh(z);
        float e1 = 1.f - h1 * h1;
        sh1[slot][p] = make_float2(h1, e1 * w0);
    }
    __syncthreads();

    float pf = 0.f, pfp = 0.f;
    if (slot < 9) {
        float s  = b2[p];
        float sd = 0.f;
#pragma unroll 8
        for (int l = 0; l < Hn; l++) {
            float  w2 = sW2[l * 64 + p];
            float2 hv = sh1[slot][l];
            s  = fmaf(w2, hv.x, s);
            sd = fmaf(w2, hv.y, sd);
        }
        float h2 = fast_tanh(s);
        float e2 = 1.f - h2 * h2;
        float w3 = W3[p];
        pf  = w3 * h2;
        pfp = w3 * e2 * sd;
    }

    const unsigned FULL = 0xffffffffu;
#pragma unroll
    for (int off = 16; off; off >>= 1) {
        pf  += __shfl_down_sync(FULL, pf,  off);
        pfp += __shfl_down_sync(FULL, pfp, off);
    }
    if (slot < 9 && (p & 31) == 0) {
        int ws = p >> 5;
        s_red[slot][ws][0] = pf;
        s_red[slot][ws][1] = pfp;
    }
    __syncthreads();
    if (slot < 9 && p == 0) {
        s_node[slot] = make_float2(
            s_red[slot][0][0] + s_red[slot][1][0] + b3[0],
            s_red[slot][0][1] + s_red[slot][1][1]);
    }
    __syncthreads();

    if (tid < 8) {
        float2 n0 = s_node[tid];
        float2 n1 = s_node[tid + 1];
        float P0 = n0.x, P1 = n1.x;
        float M0 = hstep * n0.y, M1 = hstep * n1.y;
        g_tab[blk * 8 + tid] = make_float4(
            P0, M0,
            3.f * (P1 - P0) - 2.f * M0 - M1,
            2.f * (P0 - P1) + M0 + M1);
    }
}

// Maskless pair body with magic-float floor (identical math to R12).
#define PAIR_BODY(XI, c0, c1, c2, st)                                        \
    {                                                                        \
        float r0 = XI.x - XJ.x, r1 = XI.y - XJ.y, r2 = XI.z - XJ.z;          \
        float d2   = fmaf(r0, r0, fmaf(r1, r1, fmaf(r2, r2, EPSf)));         \
        float rinv = rsqrtf(d2);                                             \
        float du   = d2 * inv_step;                                          \
        float u    = fminf(du * rinv, UMAXf);                                \
        float uf   = __fadd_rz(u, MAGICf);                                   \
        int   k    = __float_as_int(uf) & 0x7FFFFF;                          \
        float wf   = u - (uf - MAGICf);                                      \
        float4 A   = stab[k];                                                \
        float q    = fmaf(A.w, wf, A.z);                                     \
        float f    = fmaf(fmaf(q, wf, A.y), wf, A.x);                        \
        float fpw  = fmaf(fmaf(A.w, wf, q + q), wf, A.y);                    \
        c0 = fmaf(r0, f, c0);                                                \
        c1 = fmaf(r1, f, c1);                                                \
        c2 = fmaf(r2, f, c2);                                                \
        st = st + fmaf(fpw * inv_step * (d2 - EPSf), rinv, 3.f * f);         \
    }

// ---------------------------------------------------------------------------
// Kernel 2: pairs + per-batch ticket finalize. 256 blocks x 512 threads
// (2 blocks/SM). Block -> (batch b = blk>>3, 32-wide i-slab). 16 warps:
// warp w owns i = ibase + w and i = ibase + 16 + w... (slab is 32 wide,
// warp w owns iA = ibase + w (w<16) and iB = iA + 16).
// ---------------------------------------------------------------------------
__global__ void __launch_bounds__(512)
pairs_kernel(const float* __restrict__ x, float* __restrict__ out)
{
    const int tid = threadIdx.x;
    const int blk = blockIdx.x;

    __shared__ float4   stab[KI];        // 4 KB
    __shared__ float4   sxs4[Nn];        // 4 KB
    __shared__ float    s_wpart[16][4];
    __shared__ unsigned s_tk;
    __shared__ float    s_m[4];

    const float inv_step = (float)KI / DMAXf;
    const float UMAXf    = (float)KI - 0.001f;

    const int b     = blk >> 3;
    const int ibase = (blk & 7) * 32;

    if (tid < Nn) {
        const float* xb = x + b * Nn * 3 + tid * 3;
        sxs4[tid] = make_float4(xb[0], xb[1], xb[2], 0.f);
    }
    if (tid < KI) stab[tid] = g_tab[tid];
    __syncthreads();

    const int w    = tid >> 5;           // 0..15
    const int lane = tid & 31;
    const int iA   = ibase + w;
    const int iB   = iA + 16;

    {
        const float4 XA = sxs4[iA];
        const float4 XB = sxs4[iB];

        float cA0 = 0.f, cA1 = 0.f, cA2 = 0.f, sTA = 0.f;
        float cB0 = 0.f, cB1 = 0.f, cB2 = 0.f, sTB = 0.f;

        float4 XJ = sxs4[lane];
#pragma unroll
        for (int jj = 0; jj < 8; jj++) {
            float4 XJn;
            if (jj < 7) XJn = sxs4[(jj + 1) * 32 + lane];
            PAIR_BODY(XA, cA0, cA1, cA2, sTA)
            PAIR_BODY(XB, cB0, cB1, cB2, sTB)
            XJ = XJn;
        }

        const unsigned FULL = 0xffffffffu;
#pragma unroll
        for (int off = 16; off; off >>= 1) {
            cA0 += __shfl_down_sync(FULL, cA0, off);
            cA1 += __shfl_down_sync(FULL, cA1, off);
            cA2 += __shfl_down_sync(FULL, cA2, off);
            sTA += __shfl_down_sync(FULL, sTA, off);
            cB0 += __shfl_down_sync(FULL, cB0, off);
            cB1 += __shfl_down_sync(FULL, cB1, off);
            cB2 += __shfl_down_sync(FULL, cB2, off);
            sTB += __shfl_down_sync(FULL, sTB, off);
        }

        if (lane == 0) {
            // Self-pair trace correction (bitwise-identical eval at d2 = EPSf).
            float rinvs = rsqrtf(EPSf);
            float us  = fminf((EPSf * inv_step) * rinvs, UMAXf);
            float ufs = __fadd_rz(us, MAGICf);
            int   ks  = __float_as_int(ufs) & 0x7FFFFF;
            float wfs = us - (ufs - MAGICf);
            float4 As = stab[ks];
            float qs  = fmaf(As.w, wfs, As.z);
            float fs  = fmaf(fmaf(qs, wfs, As.y), wfs, As.x);
            sTA -= 3.f * fs;
            sTB -= 3.f * fs;

            const float invNm1 = 1.f / (float)(Nn - 1);
            float vA0 = cA0 * invNm1, vA1 = cA1 * invNm1, vA2 = cA2 * invNm1;
            float vB0 = cB0 * invNm1, vB1 = cB1 * invNm1, vB2 = cB2 * invNm1;
            float tAB = (sTA + sTB) * invNm1;

            int rA = b * Nn + iA;
            int rB = b * Nn + iB;
            g_v[rA * 3 + 0] = vA0;
            g_v[rA * 3 + 1] = vA1;
            g_v[rA * 3 + 2] = vA2;
            g_v[rB * 3 + 0] = vB0;
            g_v[rB * 3 + 1] = vB1;
            g_v[rB * 3 + 2] = vB2;

            s_wpart[w][0] = vA0 + vB0;
            s_wpart[w][1] = vA1 + vB1;
            s_wpart[w][2] = vA2 + vB2;
            s_wpart[w][3] = tAB;
        }
        __syncthreads();
        if (tid < 4) {
            float acc = 0.f;
#pragma unroll
            for (int ww = 0; ww < 16; ww++) acc += s_wpart[ww][tid];
            atomicAdd(&g_bsum[b * 4 + tid], acc);
        }
        __syncthreads();
    }

    // per-batch ticket: 8th arriver finalizes this batch
    if (tid == 0) {
        __threadfence();
        s_tk = atomicAdd(&g_ticket[b], 1u);
        if (s_tk == 7) __threadfence();
    }
    __syncthreads();

    if (s_tk == 7) {
        if (tid < 4) s_m[tid] = g_bsum[b * 4 + tid];
        __syncthreads();

        const float invN = 1.f / (float)Nn;
        const float m0 = s_m[0] * invN;
        const float m1 = s_m[1] * invN;
        const float m2 = s_m[2] * invN;

        for (int idx = tid; idx < Nn * 3; idx += 512) {
            int c = idx - (idx / 3) * 3;
            float mm = (c == 0) ? m0 : ((c == 1) ? m1 : m2);
            out[b * (Nn * 3) + idx] = g_v[b * (Nn * 3) + idx] - mm;
        }
        if (tid == 0)
            out[Bn * Nn * 3 + b] = s_m[3] * (1.f - 1.f / (float)Nn);

        __syncthreads();
        if (tid < 4) g_bsum[b * 4 + tid] = 0.f;
        if (tid == 0) g_ticket[b] = 0u;
    }
}

// ---------------------------------------------------------------------------
extern "C" void kernel_launch(void* const* d_in, const int* in_sizes, int n_in,
                              void* d_out, int out_size)
{
    const float* t  = (const float*)d_in[0];
    const float* x  = (const float*)d_in[1];
    const float* W1 = (const float*)d_in[2];
    const float* b1 = (const float*)d_in[3];
    const float* W2 = (const float*)d_in[4];
    const float* b2 = (const float*)d_in[5];
    const float* W3 = (const float*)d_in[6];
    const float* b3 = (const float*)d_in[7];

    table_kernel<<<32, 1024>>>(t, W1, b1, W2, b2, W3, b3);
    pairs_kernel<<<256, 512>>>(x, (float*)d_out);
}